// round 13
// baseline (speedup 1.0000x reference)
#include <cuda_runtime.h>

// IntraLoss: loss = (1/N) * sum_n || features[n] - center[labels[n]] ||_2
// N=32768, C=1000, D=512.
//
// Fused single kernel, 512 blocks x 256 threads, ALL resident (<=5 blocks/SM
// via launch_bounds) so grid-wide spin barriers are safe.
// Phase 1: label histogram.  Phase 2: exclusive scan (block 0).
// Phase 3: scatter into label-sorted order (packed row|lbl<<20).
// Phase 4: each warp processes 8 consecutive sorted positions, 32 lanes/row,
//          with the center row cached in registers (reloaded only on label
//          change) -> inner loop issues ONLY feature LDGs.
// Last block folds partials and resets all globals for graph replay.

#define NROWS 32768
#define NCLS  1000
#define DDIM  512
#define NBLK  512
#define NTHREADS 256
#define WARPS_PER_BLK 8
#define ROWS_PER_WARP 8

__device__ int g_counts[NCLS];
__device__ int g_cursor[NCLS];
__device__ int g_order[NROWS];
__device__ float g_partials[NBLK];
__device__ unsigned int g_counter = 0;
__device__ unsigned int g_barx[3];

__device__ __forceinline__ void grid_barrier(int i) {
    __syncthreads();
    if (threadIdx.x == 0) {
        __threadfence();
        atomicAdd(&g_barx[i], 1u);
        while (*((volatile unsigned int*)&g_barx[i]) < NBLK) { }
        __threadfence();
    }
    __syncthreads();
}

__global__ __launch_bounds__(NTHREADS, 5) void intra_loss_kernel(
    const float4* __restrict__ feats,    // [N, D/4]
    const int* __restrict__ labels,      // [N]
    const float4* __restrict__ center,   // [C, D/4]
    float* __restrict__ out)
{
    const int tid  = threadIdx.x;
    const int lane = tid & 31;
    const int wib  = tid >> 5;

    // ---------- Phase 1: histogram ----------
    for (int i = blockIdx.x * NTHREADS + tid; i < NROWS; i += NBLK * NTHREADS) {
        int lbl = labels[i];
        lbl = min(max(lbl, 0), NCLS - 1);
        atomicAdd(&g_counts[lbl], 1);
    }
    grid_barrier(0);

    // ---------- Phase 2: exclusive scan over 1000 counts (block 0) ----------
    if (blockIdx.x == 0) {
        __shared__ int wsum[8];
        int c[4];
        int loc = 0;
        #pragma unroll
        for (int j = 0; j < 4; j++) {
            int idx = tid * 4 + j;
            c[j] = (idx < NCLS) ? g_counts[idx] : 0;
            loc += c[j];
        }
        int v = loc;                         // inclusive warp scan
        #pragma unroll
        for (int off = 1; off < 32; off <<= 1) {
            int n = __shfl_up_sync(0xffffffffu, v, off);
            if (lane >= off) v += n;
        }
        if (lane == 31) wsum[wib] = v;
        __syncthreads();
        if (tid == 0) {
            int run = 0;
            #pragma unroll
            for (int k = 0; k < 8; k++) { int t2 = wsum[k]; wsum[k] = run; run += t2; }
        }
        __syncthreads();
        int base = wsum[wib] + v - loc;      // exclusive base for this thread
        #pragma unroll
        for (int j = 0; j < 4; j++) {
            int idx = tid * 4 + j;
            if (idx < NCLS) g_cursor[idx] = base;
            base += c[j];
        }
    }
    grid_barrier(1);

    // ---------- Phase 3: scatter into sorted order ----------
    for (int i = blockIdx.x * NTHREADS + tid; i < NROWS; i += NBLK * NTHREADS) {
        int lbl = labels[i];
        lbl = min(max(lbl, 0), NCLS - 1);
        int k = atomicAdd(&g_cursor[lbl], 1);
        g_order[k] = i | (lbl << 20);
    }
    grid_barrier(2);

    // ---------- Phase 4: compute ----------
    const int warpG = blockIdx.x * WARPS_PER_BLK + wib;
    const int pos0  = warpG * ROWS_PER_WARP;

    float dsum = 0.0f;
    int cached_lbl = -1;
    float4 C0, C1, C2, C3;
    C0 = C1 = C2 = C3 = make_float4(0.f, 0.f, 0.f, 0.f);

    #pragma unroll 1
    for (int p = 0; p < ROWS_PER_WARP; p++) {
        const int e   = g_order[pos0 + p];      // broadcast (uniform) load
        const int row = e & 0xFFFFF;
        const int lbl = e >> 20;

        if (lbl != cached_lbl) {                // uniform branch
            const float4* cr = center + (size_t)lbl * (DDIM / 4) + lane;
            C0 = cr[0];
            C1 = cr[32];
            C2 = cr[64];
            C3 = cr[96];
            cached_lbl = lbl;
        }

        const float4* fr = feats + (size_t)row * (DDIM / 4) + lane;
        float4 A0 = __ldcs(fr + 0);
        float4 A1 = __ldcs(fr + 32);
        float4 A2 = __ldcs(fr + 64);
        float4 A3 = __ldcs(fr + 96);

        float acc0 = 0.f, acc1 = 0.f, d;
        d = A0.x - C0.x; acc0 = fmaf(d, d, acc0);
        d = A0.y - C0.y; acc1 = fmaf(d, d, acc1);
        d = A0.z - C0.z; acc0 = fmaf(d, d, acc0);
        d = A0.w - C0.w; acc1 = fmaf(d, d, acc1);
        d = A1.x - C1.x; acc0 = fmaf(d, d, acc0);
        d = A1.y - C1.y; acc1 = fmaf(d, d, acc1);
        d = A1.z - C1.z; acc0 = fmaf(d, d, acc0);
        d = A1.w - C1.w; acc1 = fmaf(d, d, acc1);
        d = A2.x - C2.x; acc0 = fmaf(d, d, acc0);
        d = A2.y - C2.y; acc1 = fmaf(d, d, acc1);
        d = A2.z - C2.z; acc0 = fmaf(d, d, acc0);
        d = A2.w - C2.w; acc1 = fmaf(d, d, acc1);
        d = A3.x - C3.x; acc0 = fmaf(d, d, acc0);
        d = A3.y - C3.y; acc1 = fmaf(d, d, acc1);
        d = A3.z - C3.z; acc0 = fmaf(d, d, acc0);
        d = A3.w - C3.w; acc1 = fmaf(d, d, acc1);
        float acc = acc0 + acc1;

        #pragma unroll
        for (int sh = 16; sh > 0; sh >>= 1)
            acc += __shfl_xor_sync(0xffffffffu, acc, sh);

        if (lane == 0) dsum += sqrtf(acc);
    }

    __shared__ float wpart[8];
    __shared__ bool is_last;
    if (lane == 0) wpart[wib] = dsum;
    __syncthreads();

    if (tid == 0) {
        float s = 0.0f;
        #pragma unroll
        for (int i = 0; i < 8; i++) s += wpart[i];
        g_partials[blockIdx.x] = s;
        __threadfence();
        unsigned int old = atomicAdd(&g_counter, 1u);
        is_last = (old == NBLK - 1);
    }
    __syncthreads();

    if (is_last) {
        float v = g_partials[tid] + g_partials[tid + 256];

        #pragma unroll
        for (int sh = 16; sh > 0; sh >>= 1)
            v += __shfl_xor_sync(0xffffffffu, v, sh);

        if (lane == 0) wpart[wib] = v;
        __syncthreads();

        if (tid == 0) {
            float w = 0.0f;
            #pragma unroll
            for (int i = 0; i < 8; i++) w += wpart[i];
            out[0] = w * (1.0f / (float)NROWS);
            g_counter = 0;
        }
        // reset globals for next graph replay
        for (int i = tid; i < NCLS; i += NTHREADS) g_counts[i] = 0;
        if (tid < 3) g_barx[tid] = 0;
    }
}

extern "C" void kernel_launch(void* const* d_in, const int* in_sizes, int n_in,
                              void* d_out, int out_size)
{
    const float4* feats  = (const float4*)d_in[0];
    const int* labels    = (const int*)d_in[1];
    const float4* center = (const float4*)d_in[2];
    float* out           = (float*)d_out;

    intra_loss_kernel<<<NBLK, NTHREADS>>>(feats, labels, center, out);
}

// round 14
// speedup vs baseline: 1.7843x; 1.7843x over previous
#include <cuda_runtime.h>

// IntraLoss: loss = (1/N) * sum_n || features[n] - center[labels[n]] ||_2
// N=32768, C=1000, D=512. features f32 [N,D], labels int32 [N], center f32 [C,D].
//
// Tuned R4: 512 blocks x 512 threads (16 warps), single wave, 4 rows/warp,
// 8 lanes/row. Software-pipelined loads (prefetch next A/B pair), dual
// accumulators. Last block folds 512 partials; counters reset for replay.

#define NROWS 32768
#define NCLS  1000
#define DDIM  512
#define NBLK  512
#define NTHREADS 512
#define NWARPS 16

__device__ float g_partials[NBLK];
__device__ unsigned int g_counter = 0;

__global__ __launch_bounds__(NTHREADS) void intra_loss_kernel(
    const float4* __restrict__ feats,    // [N, D/4]
    const int* __restrict__ labels,      // [N] int32
    const float4* __restrict__ center,   // [C, D/4]
    float* __restrict__ out)
{
    const int tid   = threadIdx.x;
    const int lane  = tid & 31;
    const int wib   = tid >> 5;                               // 0..15
    const int warpG = blockIdx.x * NWARPS + wib;              // 0..8191
    const int g     = lane >> 3;                              // group 0..3
    const int l     = lane & 7;                               // lane in group
    const int row   = (warpG << 2) + g;                       // 4 rows per warp

    int lbl = labels[row];
    lbl = min(max(lbl, 0), NCLS - 1);

    const float4* fr = feats  + (size_t)row * (DDIM / 4) + l;
    const float4* cr = center + (size_t)lbl * (DDIM / 4) + l;

    // software pipeline: keep one A/B pair in flight ahead of compute
    float4 A = fr[0];
    float4 B = cr[0];

    float acc0 = 0.0f, acc1 = 0.0f;

    #pragma unroll
    for (int i = 0; i < 15; i++) {
        float4 An = fr[(i + 1) * 8];
        float4 Bn = cr[(i + 1) * 8];
        float d;
        d = A.x - B.x; acc0 = fmaf(d, d, acc0);
        d = A.y - B.y; acc1 = fmaf(d, d, acc1);
        d = A.z - B.z; acc0 = fmaf(d, d, acc0);
        d = A.w - B.w; acc1 = fmaf(d, d, acc1);
        A = An;
        B = Bn;
    }
    {
        float d;
        d = A.x - B.x; acc0 = fmaf(d, d, acc0);
        d = A.y - B.y; acc1 = fmaf(d, d, acc1);
        d = A.z - B.z; acc0 = fmaf(d, d, acc0);
        d = A.w - B.w; acc1 = fmaf(d, d, acc1);
    }
    float acc = acc0 + acc1;

    // reduce within 8-lane group (all 4 rows in parallel)
    acc += __shfl_xor_sync(0xffffffffu, acc, 1);
    acc += __shfl_xor_sync(0xffffffffu, acc, 2);
    acc += __shfl_xor_sync(0xffffffffu, acc, 4);

    // one sqrt per row (group leaders), zeros elsewhere
    float dres = (l == 0) ? sqrtf(acc) : 0.0f;

    // sum the 4 row-distances across groups
    dres += __shfl_xor_sync(0xffffffffu, dres, 8);
    dres += __shfl_xor_sync(0xffffffffu, dres, 16);

    __shared__ float smem[NWARPS];
    __shared__ bool is_last;
    if (lane == 0) smem[wib] = dres;
    __syncthreads();

    if (tid == 0) {
        float s = 0.0f;
        #pragma unroll
        for (int i = 0; i < NWARPS; i++) s += smem[i];
        g_partials[blockIdx.x] = s;
        __threadfence();
        unsigned int old = atomicAdd(&g_counter, 1u);
        is_last = (old == NBLK - 1);
    }
    __syncthreads();

    if (is_last) {
        float v = (tid < NBLK) ? g_partials[tid] : 0.0f;

        #pragma unroll
        for (int s = 16; s > 0; s >>= 1)
            v += __shfl_xor_sync(0xffffffffu, v, s);

        __shared__ float smem2[NWARPS];
        if (lane == 0) smem2[wib] = v;
        __syncthreads();

        if (tid == 0) {
            float w = 0.0f;
            #pragma unroll
            for (int i = 0; i < NWARPS; i++) w += smem2[i];
            out[0] = w * (1.0f / (float)NROWS);
            g_counter = 0;   // reset for next graph replay
        }
    }
}

extern "C" void kernel_launch(void* const* d_in, const int* in_sizes, int n_in,
                              void* d_out, int out_size)
{
    const float4* feats  = (const float4*)d_in[0];
    const int* labels    = (const int*)d_in[1];
    const float4* center = (const float4*)d_in[2];
    float* out           = (float*)d_out;

    intra_loss_kernel<<<NBLK, NTHREADS>>>(feats, labels, center, out);
}

// round 15
// speedup vs baseline: 1.7887x; 1.0025x over previous
#include <cuda_runtime.h>

// IntraLoss: loss = (1/N) * sum_n || features[n] - center[labels[n]] ||_2
// N=32768, C=1000, D=512. features f32 [N,D], labels int32 [N], center f32 [C,D].
//
// Final kernel (R4 configuration — measured optimum over 11 variants):
// 1024 blocks x 256 threads, single wave. Each warp handles 4 rows,
// 8 lanes per row (each lane: 16 float4 feature + 16 float4 center loads).
// Block partials -> device array; the last block to finish performs the
// final reduction in the same launch and resets the counter for graph replay.

#define NROWS 32768
#define NCLS  1000
#define DDIM  512
#define NBLK  1024

__device__ float g_partials[NBLK];
__device__ unsigned int g_counter = 0;

__global__ __launch_bounds__(256) void intra_loss_kernel(
    const float4* __restrict__ feats,    // [N, D/4]
    const int* __restrict__ labels,      // [N] int32
    const float4* __restrict__ center,   // [C, D/4]
    float* __restrict__ out)
{
    const int lane  = threadIdx.x & 31;
    const int wib   = threadIdx.x >> 5;                      // 0..7
    const int warpG = (blockIdx.x << 3) + wib;               // 0..8191
    const int g     = lane >> 3;                             // group 0..3
    const int l     = lane & 7;                              // lane in group
    const int row   = (warpG << 2) + g;                      // 4 rows per warp

    int lbl = labels[row];
    lbl = min(max(lbl, 0), NCLS - 1);

    const float4* fr = feats  + (size_t)row * (DDIM / 4);
    const float4* cr = center + (size_t)lbl * (DDIM / 4);

    float acc = 0.0f;
    #pragma unroll
    for (int i = 0; i < 16; i++) {
        float4 a = fr[l + i * 8];
        float4 b = __ldg(&cr[l + i * 8]);
        float dx = a.x - b.x;
        float dy = a.y - b.y;
        float dz = a.z - b.z;
        float dw = a.w - b.w;
        acc = fmaf(dx, dx, acc);
        acc = fmaf(dy, dy, acc);
        acc = fmaf(dz, dz, acc);
        acc = fmaf(dw, dw, acc);
    }

    // reduce within 8-lane group (all 4 rows in parallel)
    acc += __shfl_xor_sync(0xffffffffu, acc, 1);
    acc += __shfl_xor_sync(0xffffffffu, acc, 2);
    acc += __shfl_xor_sync(0xffffffffu, acc, 4);

    // one sqrt per row (group leaders), zeros elsewhere
    float d = (l == 0) ? sqrtf(acc) : 0.0f;

    // sum the 4 row-distances across groups
    d += __shfl_xor_sync(0xffffffffu, d, 8);
    d += __shfl_xor_sync(0xffffffffu, d, 16);

    __shared__ float smem[8];
    __shared__ bool is_last;
    if (lane == 0) smem[wib] = d;
    __syncthreads();

    if (threadIdx.x == 0) {
        float s = 0.0f;
        #pragma unroll
        for (int i = 0; i < 8; i++) s += smem[i];
        g_partials[blockIdx.x] = s;
        __threadfence();
        unsigned int old = atomicAdd(&g_counter, 1u);
        is_last = (old == NBLK - 1);
    }
    __syncthreads();

    if (is_last) {
        // 256 threads, each reads 4 partials (L2-hot)
        float v = 0.0f;
        #pragma unroll
        for (int i = 0; i < 4; i++)
            v += g_partials[threadIdx.x + i * 256];

        #pragma unroll
        for (int s = 16; s > 0; s >>= 1)
            v += __shfl_xor_sync(0xffffffffu, v, s);

        __shared__ float smem2[8];
        if (lane == 0) smem2[wib] = v;
        __syncthreads();

        if (threadIdx.x == 0) {
            float w = 0.0f;
            #pragma unroll
            for (int i = 0; i < 8; i++) w += smem2[i];
            out[0] = w * (1.0f / (float)NROWS);
            g_counter = 0;   // reset for next graph replay
        }
    }
}

extern "C" void kernel_launch(void* const* d_in, const int* in_sizes, int n_in,
                              void* d_out, int out_size)
{
    const float4* feats  = (const float4*)d_in[0];
    const int* labels    = (const int*)d_in[1];
    const float4* center = (const float4*)d_in[2];
    float* out           = (float*)d_out;

    intra_loss_kernel<<<NBLK, 256>>>(feats, labels, center, out);
}